// round 15
// baseline (speedup 1.0000x reference)
#include <cuda_runtime.h>
#include <cuda_fp16.h>
#include <math.h>
#include <stdint.h>

#define S_TOK 8192
#define H_DIM 1024
#define N_EXP 64
#define CAP 512
#define D_FF 2048
#define NROWS (N_EXP * CAP)  // 32768

// ---------------- scratch (device globals) ----------------------------------
__device__ float  g_xn[(size_t)S_TOK * H_DIM];    // 32 MB (router, fp32)
__device__ __half g_xnh[(size_t)S_TOK * H_DIM];   // 16 MB
__device__ __half g_hh[(size_t)NROWS * D_FF];     // 128 MB
__device__ __half g_od[(size_t)NROWS * H_DIM];    // 64 MB
__device__ int    g_row_tok[NROWS];
__device__ int    g_count[N_EXP];
__device__ int    g_pair_idx[S_TOK * 2];
__device__ float  g_pair_w[S_TOK * 2];

// ---------------- helpers -----------------------------------------------------
__device__ __forceinline__ uint32_t smem_u32(const void* p) {
    uint32_t a;
    asm("{ .reg .u64 t; cvta.to.shared.u64 t, %1; cvt.u32.u64 %0, t; }"
        : "=r"(a) : "l"(p));
    return a;
}
__device__ __forceinline__ void ldsm4(uint32_t* r, uint32_t addr) {
    asm volatile("ldmatrix.sync.aligned.m8n8.x4.shared.b16 {%0,%1,%2,%3}, [%4];"
                 : "=r"(r[0]), "=r"(r[1]), "=r"(r[2]), "=r"(r[3]) : "r"(addr));
}
__device__ __forceinline__ void mma_f16(float* d, const uint32_t* a,
                                        uint32_t b0, uint32_t b1) {
    asm volatile("mma.sync.aligned.m16n8k16.row.col.f32.f16.f16.f32 "
                 "{%0,%1,%2,%3}, {%4,%5,%6,%7}, {%8,%9}, {%0,%1,%2,%3};"
                 : "+f"(d[0]), "+f"(d[1]), "+f"(d[2]), "+f"(d[3])
                 : "r"(a[0]), "r"(a[1]), "r"(a[2]), "r"(a[3]), "r"(b0), "r"(b1));
}
__device__ __forceinline__ void cp16(uint32_t dst, const void* src, uint32_t sz) {
    asm volatile("cp.async.cg.shared.global [%0], [%1], 16, %2;"
                 :: "r"(dst), "l"(src), "r"(sz) : "memory");
}
#define CP_COMMIT() asm volatile("cp.async.commit_group;" ::: "memory")
#define CP_WAIT1()  asm volatile("cp.async.wait_group 1;" ::: "memory")

__device__ __forceinline__ uint32_t pack_h2(float a, float b) {
    __half2 t = __floats2half2_rn(a, b);
    return *reinterpret_cast<uint32_t*>(&t);
}
__device__ __forceinline__ float silu_f(float v) { return v / (1.0f + expf(-v)); }

// smem geometry: BK=32 fp16 per row = 64B payload, 80B stride (conflict-free)
#define RB 80
#define A_OFF 0
#define B_OFF (128 * RB)      // 10240
#define STAGE (2 * 128 * RB)  // 20480
#define SMEM_SZ (3 * STAGE)   // 61440 (3-stage pipeline)

// ---------------- 1: RMSNorm (+ fp16 round; block 0 zeroes counters) ----------
__global__ void k_rmsnorm(const float* __restrict__ x, const float* __restrict__ w) {
    int tok = blockIdx.x;
    int t = threadIdx.x;
    if (blockIdx.x == 0 && t < N_EXP) g_count[t] = 0;
    float4 v = ((const float4*)(x + (size_t)tok * H_DIM))[t];
    float ss = v.x * v.x + v.y * v.y + v.z * v.z + v.w * v.w;
#pragma unroll
    for (int o = 16; o > 0; o >>= 1) ss += __shfl_xor_sync(0xffffffffu, ss, o);
    __shared__ float red[8];
    if ((t & 31) == 0) red[t >> 5] = ss;
    __syncthreads();
    float tot = red[0] + red[1] + red[2] + red[3] + red[4] + red[5] + red[6] + red[7];
    float scale = rsqrtf(tot * (1.0f / H_DIM) + 1e-6f);
    float4 wv = ((const float4*)w)[t];
    float4 o;
    o.x = v.x * scale * wv.x; o.y = v.y * scale * wv.y;
    o.z = v.z * scale * wv.z; o.w = v.w * scale * wv.w;
    ((float4*)(g_xn + (size_t)tok * H_DIM))[t] = o;
    uint2 H;
    H.x = pack_h2(o.x, o.y); H.y = pack_h2(o.z, o.w);
    *(uint2*)(g_xnh + (size_t)tok * H_DIM + t * 4) = H;
}

// ---------------- 2: router + top2 + slot assign ------------------------------
// 256 blocks x 32 tokens, fp32 (routing must match fp32 reference).
// K-chunk 32, double-buffered smem, ONE syncthreads per chunk.
__global__ void k_router(const float* __restrict__ rw) {
    __shared__ float As[2][32][33];
    __shared__ float Bs[2][32][65];
    __shared__ float Ss[32][65];
    int t = threadIdx.x;
    int tok0 = blockIdx.x * 32;
    int ty = t >> 4, tx = t & 15;
    float acc[2][4];
#pragma unroll
    for (int i = 0; i < 2; i++)
#pragma unroll
        for (int j = 0; j < 4; j++) acc[i][j] = 0.0f;

    int lrA = t >> 3;          // 0..31 token
    int lkA = (t & 7) * 4;     // 0..28
    int lrB = t >> 2;          // 0..63 expert
    int lkB = (t & 3) * 8;     // 0,8,16,24
    const float* ap = g_xn + (size_t)(tok0 + lrA) * H_DIM + lkA;
    const float* bp = rw + (size_t)lrB * H_DIM + lkB;

    // prologue: chunk 0 -> buffer 0
    float4 pa = *(const float4*)(ap);
    float4 pb0 = *(const float4*)(bp);
    float4 pb1 = *(const float4*)(bp + 4);
    As[0][lkA + 0][lrA] = pa.x; As[0][lkA + 1][lrA] = pa.y;
    As[0][lkA + 2][lrA] = pa.z; As[0][lkA + 3][lrA] = pa.w;
    Bs[0][lkB + 0][lrB] = pb0.x; Bs[0][lkB + 1][lrB] = pb0.y;
    Bs[0][lkB + 2][lrB] = pb0.z; Bs[0][lkB + 3][lrB] = pb0.w;
    Bs[0][lkB + 4][lrB] = pb1.x; Bs[0][lkB + 5][lrB] = pb1.y;
    Bs[0][lkB + 6][lrB] = pb1.z; Bs[0][lkB + 7][lrB] = pb1.w;
    __syncthreads();

    const int NCH = H_DIM / 32;  // 32
#pragma unroll 1
    for (int c = 0; c < NCH; c++) {
        int cur = c & 1;
        if (c + 1 < NCH) {
            pa = *(const float4*)(ap + (c + 1) * 32);
            pb0 = *(const float4*)(bp + (c + 1) * 32);
            pb1 = *(const float4*)(bp + (c + 1) * 32 + 4);
        }
#pragma unroll
        for (int kk = 0; kk < 32; kk++) {
            float a[2], b[4];
#pragma unroll
            for (int i = 0; i < 2; i++) a[i] = As[cur][kk][ty * 2 + i];
#pragma unroll
            for (int j = 0; j < 4; j++) b[j] = Bs[cur][kk][tx * 4 + j];
#pragma unroll
            for (int i = 0; i < 2; i++)
#pragma unroll
                for (int j = 0; j < 4; j++) acc[i][j] = fmaf(a[i], b[j], acc[i][j]);
        }
        if (c + 1 < NCH) {
            int nxt = cur ^ 1;
            As[nxt][lkA + 0][lrA] = pa.x; As[nxt][lkA + 1][lrA] = pa.y;
            As[nxt][lkA + 2][lrA] = pa.z; As[nxt][lkA + 3][lrA] = pa.w;
            Bs[nxt][lkB + 0][lrB] = pb0.x; Bs[nxt][lkB + 1][lrB] = pb0.y;
            Bs[nxt][lkB + 2][lrB] = pb0.z; Bs[nxt][lkB + 3][lrB] = pb0.w;
            Bs[nxt][lkB + 4][lrB] = pb1.x; Bs[nxt][lkB + 5][lrB] = pb1.y;
            Bs[nxt][lkB + 6][lrB] = pb1.z; Bs[nxt][lkB + 7][lrB] = pb1.w;
        }
        __syncthreads();
    }

#pragma unroll
    for (int i = 0; i < 2; i++)
#pragma unroll
        for (int j = 0; j < 4; j++) Ss[ty * 2 + i][tx * 4 + j] = acc[i][j];
    __syncthreads();

    if (t < 32) {
        int tok = tok0 + t;
        float v1 = -1e30f, v2 = -1e30f;
        int i1 = 0, i2 = 0;
#pragma unroll 4
        for (int e = 0; e < N_EXP; e++) {
            float s = Ss[t][e];
            if (s > v1) { v2 = v1; i2 = i1; v1 = s; i1 = e; }
            else if (s > v2) { v2 = s; i2 = e; }
        }
        float ex = expf(v2 - v1);
        float wB = ex / (1.0f + ex);
        float wA = 1.0f - wB;

        int s1 = atomicAdd(&g_count[i1], 1);
        if (s1 < CAP) {
            g_row_tok[i1 * CAP + s1] = tok;
            g_pair_idx[tok * 2] = i1 * CAP + s1;
            g_pair_w[tok * 2] = wA;
        } else g_pair_idx[tok * 2] = -1;
        int s2 = atomicAdd(&g_count[i2], 1);
        if (s2 < CAP) {
            g_row_tok[i2 * CAP + s2] = tok;
            g_pair_idx[tok * 2 + 1] = i2 * CAP + s2;
            g_pair_w[tok * 2 + 1] = wB;
        } else g_pair_idx[tok * 2 + 1] = -1;
    }
}

// ---------------- GEMM core: fp16, A via cp.async, B fused fp32->fp16 ---------
// CTA 128x128, 256 threads, 8 warps (2 wm x 4 wn), warp tile 64x32, BK=32,
// 3-stage smem ring. Store mapping row=t&127, half=t>>7: quarter-warps cover
// 8 consecutive rows at fixed half -> stride-20-word pattern covers all 32
// banks -> STS.128 and cp.async writes are conflict-free (LDSM unchanged).

#define LDGB(dst, src, c)                                     \
    {                                                         \
        const float4* _p = (const float4*)((src) + (c) * 32); \
        dst[0] = _p[0]; dst[1] = _p[1];                        \
        dst[2] = _p[2]; dst[3] = _p[3];                        \
    }
#define STSB(buf, sts, br)                                                        \
    {                                                                             \
        *(uint4*)((buf) + B_OFF + (sts)) =                                        \
            make_uint4(pack_h2(br[0].x, br[0].y), pack_h2(br[0].z, br[0].w),      \
                       pack_h2(br[1].x, br[1].y), pack_h2(br[1].z, br[1].w));     \
        *(uint4*)((buf) + B_OFF + (sts) + 16) =                                   \
            make_uint4(pack_h2(br[2].x, br[2].y), pack_h2(br[2].z, br[2].w),      \
                       pack_h2(br[3].x, br[3].y), pack_h2(br[3].z, br[3].w));     \
    }

// GEMM1: h = silu(xn[gather] @ w1[e]^T)
__global__ void __launch_bounds__(256, 2) k_gemm1(const float* __restrict__ w1) {
    int e = blockIdx.z;
    int cnt = min(g_count[e], CAP);
    int m0 = blockIdx.y * 128;
    if (m0 >= cnt) return;
    int n0 = blockIdx.x * 128;

    extern __shared__ char sm[];
    __shared__ int stok[128];
    int t = threadIdx.x, lane = t & 31, w = t >> 5;
    if (t < 128) {
        int s = m0 + t;
        stok[t] = (s < cnt) ? g_row_tok[e * CAP + s] : -1;
    }
    __syncthreads();

    int row = t & 127;      // conflict-free store mapping
    int half = t >> 7;
    int atok = stok[row];
    uint32_t asz = (atok >= 0) ? 16u : 0u;
    const __half* a_src = g_xnh + ((atok >= 0) ? (size_t)atok * H_DIM : 0) + half * 16;
    const float* b_src = w1 + ((size_t)e * D_FF + n0 + row) * H_DIM + half * 16;
    uint32_t smb = smem_u32(sm);
    uint32_t sts = row * RB + half * 32;

    int wm = (w & 1) * 64;
    int wn = (w >> 1) * 32;
    uint32_t lm = (lane & 15) * RB + ((lane >> 4) << 4);
    uint32_t aoff = A_OFF + wm * RB + lm;
    uint32_t boff = B_OFF + wn * RB + lm;

    const int NC = H_DIM / 32;  // 32

    float4 br[4];
    LDGB(br, b_src, 0);
    STSB(sm, sts, br);
    LDGB(br, b_src, 1);
#pragma unroll
    for (int s = 0; s < 2; s++) {
        uint32_t d = smb + s * STAGE + sts;
        cp16(d + A_OFF, a_src + s * 32, asz);
        cp16(d + A_OFF + 16, a_src + s * 32 + 8, asz);
        CP_COMMIT();
    }

    float acc[4][4][4];
#pragma unroll
    for (int mf = 0; mf < 4; mf++)
#pragma unroll
        for (int nf = 0; nf < 4; nf++)
#pragma unroll
            for (int k = 0; k < 4; k++) acc[mf][nf][k] = 0.0f;

    uint32_t rd = smb;                        // compute stage (c)
    char*    w1s = sm + STAGE;                // STSB stage (c+1)
    uint32_t w2s = smb + 2 * STAGE;           // cp.async stage (c+2)
    const uint32_t smt = smb + 3 * STAGE;
    char* const smt_p = sm + 3 * STAGE;

#pragma unroll 1
    for (int c = 0; c < NC; c++) {
        CP_WAIT1();
        __syncthreads();
        if (c + 1 < NC) STSB(w1s, sts, br);
        if (c + 2 < NC) {
            LDGB(br, b_src, c + 2);
            uint32_t d = w2s + sts;
            cp16(d + A_OFF, a_src + (c + 2) * 32, asz);
            cp16(d + A_OFF + 16, a_src + (c + 2) * 32 + 8, asz);
        }
        CP_COMMIT();
#pragma unroll
        for (int kk = 0; kk < 2; kk++) {
            uint32_t ko = kk * 32;
            uint32_t ah[4][4], bh[2][4];
#pragma unroll
            for (int mf = 0; mf < 4; mf++) ldsm4(ah[mf], rd + aoff + mf * (16 * RB) + ko);
#pragma unroll
            for (int g = 0; g < 2; g++) ldsm4(bh[g], rd + boff + g * (16 * RB) + ko);
#pragma unroll
            for (int mf = 0; mf < 4; mf++)
#pragma unroll
                for (int nf = 0; nf < 4; nf++)
                    mma_f16(acc[mf][nf], ah[mf], bh[nf >> 1][nf & 1], bh[nf >> 1][(nf & 1) + 2]);
        }
        rd += STAGE;  if (rd == smt) rd = smb;
        w1s += STAGE; if (w1s == smt_p) w1s = sm;
        w2s += STAGE; if (w2s == smt) w2s = smb;
    }

    int rbase = m0 + wm + (lane >> 2);
    size_t eb = (size_t)e * CAP;
#pragma unroll
    for (int mf = 0; mf < 4; mf++) {
#pragma unroll
        for (int nf = 0; nf < 4; nf++) {
            int col = n0 + wn + nf * 8 + (lane & 3) * 2;
#pragma unroll
            for (int hh = 0; hh < 2; hh++) {
                size_t r = eb + rbase + mf * 16 + hh * 8;
                float s0 = silu_f(acc[mf][nf][hh * 2]);
                float s1 = silu_f(acc[mf][nf][hh * 2 + 1]);
                *(uint32_t*)(g_hh + r * D_FF + col) = pack_h2(s0, s1);
            }
        }
    }
}

// GEMM2: od = h @ w2[e]^T  (od stored fp16)
__global__ void __launch_bounds__(256, 2) k_gemm2(const float* __restrict__ w2) {
    int e = blockIdx.z;
    int cnt = min(g_count[e], CAP);
    int m0 = blockIdx.y * 128;
    if (m0 >= cnt) return;
    int n0 = blockIdx.x * 128;

    extern __shared__ char sm[];
    int t = threadIdx.x, lane = t & 31, w = t >> 5;

    int row = t & 127;
    int half = t >> 7;
    const __half* a_src = g_hh + ((size_t)e * CAP + m0 + row) * D_FF + half * 16;
    const float* b_src = w2 + ((size_t)e * H_DIM + n0 + row) * D_FF + half * 16;
    uint32_t smb = smem_u32(sm);
    uint32_t sts = row * RB + half * 32;

    int wm = (w & 1) * 64;
    int wn = (w >> 1) * 32;
    uint32_t lm = (lane & 15) * RB + ((lane >> 4) << 4);
    uint32_t aoff = A_OFF + wm * RB + lm;
    uint32_t boff = B_OFF + wn * RB + lm;

    const int NC = D_FF / 32;  // 64

    float4 br[4];
    LDGB(br, b_src, 0);
    STSB(sm, sts, br);
    LDGB(br, b_src, 1);
#pragma unroll
    for (int s = 0; s < 2; s++) {
        uint32_t d = smb + s * STAGE + sts;
        cp16(d + A_OFF, a_src + s * 32, 16);
        cp16(d + A_OFF + 16, a_src + s * 32 + 8, 16);
        CP_COMMIT();
    }

    float acc[4][4][4];
#pragma unroll
    for (int mf = 0; mf < 4; mf++)
#pragma unroll
        for (int nf = 0; nf < 4; nf++)
#pragma unroll
            for (int k = 0; k < 4; k++) acc[mf][nf][k] = 0.0f;

    uint32_t rd = smb;
    char*    w1s = sm + STAGE;
    uint32_t w2s = smb + 2 * STAGE;
    const uint32_t smt = smb + 3 * STAGE;
    char* const smt_p = sm + 3 * STAGE;

#pragma unroll 1
    for (int c = 0; c < NC; c++) {
        CP_WAIT1();
        __syncthreads();
        if (c + 1 < NC) STSB(w1s, sts, br);
        if (c + 2 < NC) {
            LDGB(br, b_src, c + 2);
            uint32_t d = w2s + sts;
            cp16(d + A_OFF, a_src + (c + 2) * 32, 16);
            cp16(d + A_OFF + 16, a_src + (c + 2) * 32 + 8, 16);
        }
        CP_COMMIT();
#pragma unroll
        for (int kk = 0; kk < 2; kk++) {
            uint32_t ko = kk * 32;
            uint32_t ah[4][4], bh[2][4];
#pragma unroll
            for (int mf = 0; mf < 4; mf++) ldsm4(ah[mf], rd + aoff + mf * (16 * RB) + ko);
#pragma unroll
            for (int g = 0; g < 2; g++) ldsm4(bh[g], rd + boff + g * (16 * RB) + ko);
#pragma unroll
            for (int mf = 0; mf < 4; mf++)
#pragma unroll
                for (int nf = 0; nf < 4; nf++)
                    mma_f16(acc[mf][nf], ah[mf], bh[nf >> 1][nf & 1], bh[nf >> 1][(nf & 1) + 2]);
        }
        rd += STAGE;  if (rd == smt) rd = smb;
        w1s += STAGE; if (w1s == smt_p) w1s = sm;
        w2s += STAGE; if (w2s == smt) w2s = smb;
    }

    int rbase = m0 + wm + (lane >> 2);
    size_t eb = (size_t)e * CAP;
#pragma unroll
    for (int mf = 0; mf < 4; mf++) {
#pragma unroll
        for (int nf = 0; nf < 4; nf++) {
            int col = n0 + wn + nf * 8 + (lane & 3) * 2;
#pragma unroll
            for (int hh = 0; hh < 2; hh++) {
                size_t r = eb + rbase + mf * 16 + hh * 8;
                *(uint32_t*)(g_od + r * H_DIM + col) =
                    pack_h2(acc[mf][nf][hh * 2], acc[mf][nf][hh * 2 + 1]);
            }
        }
    }
}

// ---------------- 5: combine (od is fp16) --------------------------------------
__global__ void k_combine(const float* __restrict__ x, float* __restrict__ out) {
    int tok = blockIdx.x;
    int t = threadIdx.x;
    int p0 = g_pair_idx[tok * 2];
    int p1 = g_pair_idx[tok * 2 + 1];
    float w0 = g_pair_w[tok * 2];
    float w1 = g_pair_w[tok * 2 + 1];
    float4 v = ((const float4*)(x + (size_t)tok * H_DIM))[t];
    if (p0 >= 0) {
        uint2 u = *(const uint2*)(g_od + (size_t)p0 * H_DIM + t * 4);
        float2 a = __half22float2(*(__half2*)&u.x);
        float2 b = __half22float2(*(__half2*)&u.y);
        v.x += w0 * a.x; v.y += w0 * a.y; v.z += w0 * b.x; v.w += w0 * b.y;
    }
    if (p1 >= 0) {
        uint2 u = *(const uint2*)(g_od + (size_t)p1 * H_DIM + t * 4);
        float2 a = __half22float2(*(__half2*)&u.x);
        float2 b = __half22float2(*(__half2*)&u.y);
        v.x += w1 * a.x; v.y += w1 * a.y; v.z += w1 * b.x; v.w += w1 * b.y;
    }
    ((float4*)(out + (size_t)tok * H_DIM))[t] = v;
}

// ---------------- launch --------------------------------------------------------
extern "C" void kernel_launch(void* const* d_in, const int* in_sizes, int n_in,
                              void* d_out, int out_size) {
    const float* x        = (const float*)d_in[0];
    const float* rms_w    = (const float*)d_in[1];
    const float* router_w = (const float*)d_in[2];
    const float* w1       = (const float*)d_in[3];
    const float* w2       = (const float*)d_in[4];
    float* out = (float*)d_out;

    static bool attr_done = false;
    if (!attr_done) {
        cudaFuncSetAttribute(k_gemm1, cudaFuncAttributeMaxDynamicSharedMemorySize, SMEM_SZ);
        cudaFuncSetAttribute(k_gemm2, cudaFuncAttributeMaxDynamicSharedMemorySize, SMEM_SZ);
        attr_done = true;
    }

    k_rmsnorm<<<S_TOK, 256>>>(x, rms_w);
    k_router<<<S_TOK / 32, 256>>>(router_w);
    k_gemm1<<<dim3(D_FF / 128, CAP / 128, N_EXP), 256, SMEM_SZ>>>(w1);
    k_gemm2<<<dim3(H_DIM / 128, CAP / 128, N_EXP), 256, SMEM_SZ>>>(w2);
    k_combine<<<S_TOK, 256>>>(x, out);
}

// round 16
// speedup vs baseline: 1.3001x; 1.3001x over previous
#include <cuda_runtime.h>
#include <cuda_fp16.h>
#include <math.h>
#include <stdint.h>

#define S_TOK 8192
#define H_DIM 1024
#define N_EXP 64
#define CAP 512
#define D_FF 2048
#define NROWS (N_EXP * CAP)  // 32768

// ---------------- scratch (device globals) ----------------------------------
__device__ float  g_scale[S_TOK];                 // rms scale per token
__device__ __half g_xnh[(size_t)S_TOK * H_DIM];   // 16 MB
__device__ __half g_hh[(size_t)NROWS * D_FF];     // 128 MB
__device__ __half g_od[(size_t)NROWS * H_DIM];    // 64 MB
__device__ int    g_row_tok[NROWS];
__device__ int    g_count[N_EXP];
__device__ int    g_pair_idx[S_TOK * 2];
__device__ float  g_pair_w[S_TOK * 2];

// ---------------- helpers -----------------------------------------------------
__device__ __forceinline__ uint32_t smem_u32(const void* p) {
    uint32_t a;
    asm("{ .reg .u64 t; cvta.to.shared.u64 t, %1; cvt.u32.u64 %0, t; }"
        : "=r"(a) : "l"(p));
    return a;
}
__device__ __forceinline__ void ldsm4(uint32_t* r, uint32_t addr) {
    asm volatile("ldmatrix.sync.aligned.m8n8.x4.shared.b16 {%0,%1,%2,%3}, [%4];"
                 : "=r"(r[0]), "=r"(r[1]), "=r"(r[2]), "=r"(r[3]) : "r"(addr));
}
__device__ __forceinline__ void mma_f16(float* d, const uint32_t* a,
                                        uint32_t b0, uint32_t b1) {
    asm volatile("mma.sync.aligned.m16n8k16.row.col.f32.f16.f16.f32 "
                 "{%0,%1,%2,%3}, {%4,%5,%6,%7}, {%8,%9}, {%0,%1,%2,%3};"
                 : "+f"(d[0]), "+f"(d[1]), "+f"(d[2]), "+f"(d[3])
                 : "r"(a[0]), "r"(a[1]), "r"(a[2]), "r"(a[3]), "r"(b0), "r"(b1));
}
__device__ __forceinline__ void cp16(uint32_t dst, const void* src, uint32_t sz) {
    asm volatile("cp.async.cg.shared.global [%0], [%1], 16, %2;"
                 :: "r"(dst), "l"(src), "r"(sz) : "memory");
}
#define CP_COMMIT() asm volatile("cp.async.commit_group;" ::: "memory")
#define CP_WAIT1()  asm volatile("cp.async.wait_group 1;" ::: "memory")

__device__ __forceinline__ uint32_t pack_h2(float a, float b) {
    __half2 t = __floats2half2_rn(a, b);
    return *reinterpret_cast<uint32_t*>(&t);
}
__device__ __forceinline__ float silu_f(float v) { return v / (1.0f + expf(-v)); }

// smem geometry: BK=32 fp16 per row = 64B payload, 80B stride (conflict-free)
#define RB 80
#define A_OFF 0
#define B_OFF (128 * RB)      // 10240
#define STAGE (2 * 128 * RB)  // 20480
#define SMEM_SZ (3 * STAGE)   // 61440 (3-stage pipeline)

// ---------------- 1: RMSNorm (fp16 out + scale; block 0 zeroes counters) ------
__global__ void k_rmsnorm(const float* __restrict__ x, const float* __restrict__ w) {
    int tok = blockIdx.x;
    int t = threadIdx.x;
    if (blockIdx.x == 0 && t < N_EXP) g_count[t] = 0;
    float4 v = ((const float4*)(x + (size_t)tok * H_DIM))[t];
    float ss = v.x * v.x + v.y * v.y + v.z * v.z + v.w * v.w;
#pragma unroll
    for (int o = 16; o > 0; o >>= 1) ss += __shfl_xor_sync(0xffffffffu, ss, o);
    __shared__ float red[8];
    if ((t & 31) == 0) red[t >> 5] = ss;
    __syncthreads();
    float tot = red[0] + red[1] + red[2] + red[3] + red[4] + red[5] + red[6] + red[7];
    float scale = rsqrtf(tot * (1.0f / H_DIM) + 1e-6f);
    if (t == 0) g_scale[tok] = scale;
    float4 wv = ((const float4*)w)[t];
    float4 o;
    o.x = v.x * scale * wv.x; o.y = v.y * scale * wv.y;
    o.z = v.z * scale * wv.z; o.w = v.w * scale * wv.w;
    uint2 H;
    H.x = pack_h2(o.x, o.y); H.y = pack_h2(o.z, o.w);
    *(uint2*)(g_xnh + (size_t)tok * H_DIM + t * 4) = H;
}

// ---------------- 2: router + top2 + slot assign ------------------------------
// 256 blocks x 32 tokens, fp32 (routing must match fp32 reference).
// Reads x directly; As = (x*scale)*rms_w — bit-identical to rmsnorm's xn.
// K-chunk 32, double-buffered smem, ONE syncthreads per chunk.
__global__ void k_router(const float* __restrict__ x,
                         const float* __restrict__ rms_w,
                         const float* __restrict__ rw) {
    __shared__ float As[2][32][33];
    __shared__ float Bs[2][32][65];
    __shared__ float Ss[32][65];
    int t = threadIdx.x;
    int tok0 = blockIdx.x * 32;
    int ty = t >> 4, tx = t & 15;
    float acc[2][4];
#pragma unroll
    for (int i = 0; i < 2; i++)
#pragma unroll
        for (int j = 0; j < 4; j++) acc[i][j] = 0.0f;

    int lrA = t >> 3;          // 0..31 token
    int lkA = (t & 7) * 4;     // 0..28
    int lrB = t >> 2;          // 0..63 expert
    int lkB = (t & 3) * 8;     // 0,8,16,24
    const float* ap = x + (size_t)(tok0 + lrA) * H_DIM + lkA;
    const float* wp = rms_w + lkA;
    const float* bp = rw + (size_t)lrB * H_DIM + lkB;
    float scaleA = g_scale[tok0 + lrA];

    // prologue: chunk 0 -> buffer 0
    float4 pa = *(const float4*)(ap);
    float4 pw = *(const float4*)(wp);
    float4 pb0 = *(const float4*)(bp);
    float4 pb1 = *(const float4*)(bp + 4);
    As[0][lkA + 0][lrA] = pa.x * scaleA * pw.x;
    As[0][lkA + 1][lrA] = pa.y * scaleA * pw.y;
    As[0][lkA + 2][lrA] = pa.z * scaleA * pw.z;
    As[0][lkA + 3][lrA] = pa.w * scaleA * pw.w;
    Bs[0][lkB + 0][lrB] = pb0.x; Bs[0][lkB + 1][lrB] = pb0.y;
    Bs[0][lkB + 2][lrB] = pb0.z; Bs[0][lkB + 3][lrB] = pb0.w;
    Bs[0][lkB + 4][lrB] = pb1.x; Bs[0][lkB + 5][lrB] = pb1.y;
    Bs[0][lkB + 6][lrB] = pb1.z; Bs[0][lkB + 7][lrB] = pb1.w;
    __syncthreads();

    const int NCH = H_DIM / 32;  // 32
#pragma unroll 1
    for (int c = 0; c < NCH; c++) {
        int cur = c & 1;
        if (c + 1 < NCH) {
            pa = *(const float4*)(ap + (c + 1) * 32);
            pw = *(const float4*)(wp + (c + 1) * 32);
            pb0 = *(const float4*)(bp + (c + 1) * 32);
            pb1 = *(const float4*)(bp + (c + 1) * 32 + 4);
        }
#pragma unroll
        for (int kk = 0; kk < 32; kk++) {
            float a[2], b[4];
#pragma unroll
            for (int i = 0; i < 2; i++) a[i] = As[cur][kk][ty * 2 + i];
#pragma unroll
            for (int j = 0; j < 4; j++) b[j] = Bs[cur][kk][tx * 4 + j];
#pragma unroll
            for (int i = 0; i < 2; i++)
#pragma unroll
                for (int j = 0; j < 4; j++) acc[i][j] = fmaf(a[i], b[j], acc[i][j]);
        }
        if (c + 1 < NCH) {
            int nxt = cur ^ 1;
            As[nxt][lkA + 0][lrA] = pa.x * scaleA * pw.x;
            As[nxt][lkA + 1][lrA] = pa.y * scaleA * pw.y;
            As[nxt][lkA + 2][lrA] = pa.z * scaleA * pw.z;
            As[nxt][lkA + 3][lrA] = pa.w * scaleA * pw.w;
            Bs[nxt][lkB + 0][lrB] = pb0.x; Bs[nxt][lkB + 1][lrB] = pb0.y;
            Bs[nxt][lkB + 2][lrB] = pb0.z; Bs[nxt][lkB + 3][lrB] = pb0.w;
            Bs[nxt][lkB + 4][lrB] = pb1.x; Bs[nxt][lkB + 5][lrB] = pb1.y;
            Bs[nxt][lkB + 6][lrB] = pb1.z; Bs[nxt][lkB + 7][lrB] = pb1.w;
        }
        __syncthreads();
    }

#pragma unroll
    for (int i = 0; i < 2; i++)
#pragma unroll
        for (int j = 0; j < 4; j++) Ss[ty * 2 + i][tx * 4 + j] = acc[i][j];
    __syncthreads();

    if (t < 32) {
        int tok = tok0 + t;
        float v1 = -1e30f, v2 = -1e30f;
        int i1 = 0, i2 = 0;
#pragma unroll 4
        for (int e = 0; e < N_EXP; e++) {
            float s = Ss[t][e];
            if (s > v1) { v2 = v1; i2 = i1; v1 = s; i1 = e; }
            else if (s > v2) { v2 = s; i2 = e; }
        }
        float ex = expf(v2 - v1);
        float wB = ex / (1.0f + ex);
        float wA = 1.0f - wB;

        int s1 = atomicAdd(&g_count[i1], 1);
        if (s1 < CAP) {
            g_row_tok[i1 * CAP + s1] = tok;
            g_pair_idx[tok * 2] = i1 * CAP + s1;
            g_pair_w[tok * 2] = wA;
        } else g_pair_idx[tok * 2] = -1;
        int s2 = atomicAdd(&g_count[i2], 1);
        if (s2 < CAP) {
            g_row_tok[i2 * CAP + s2] = tok;
            g_pair_idx[tok * 2 + 1] = i2 * CAP + s2;
            g_pair_w[tok * 2 + 1] = wB;
        } else g_pair_idx[tok * 2 + 1] = -1;
    }
}

// ---------------- GEMM core: fp16, A via cp.async, B fused fp32->fp16 ---------
// CTA 128x128, 256 threads, 8 warps (2 wm x 4 wn), warp tile 64x32, BK=32,
// 3-stage smem ring (round-7/12/14 champion configuration — FROZEN).

#define LDGB(dst, src, c)                                     \
    {                                                         \
        const float4* _p = (const float4*)((src) + (c) * 32); \
        dst[0] = _p[0]; dst[1] = _p[1];                        \
        dst[2] = _p[2]; dst[3] = _p[3];                        \
    }
#define STSB(buf, sts, br)                                                        \
    {                                                                             \
        *(uint4*)((buf) + B_OFF + (sts)) =                                        \
            make_uint4(pack_h2(br[0].x, br[0].y), pack_h2(br[0].z, br[0].w),      \
                       pack_h2(br[1].x, br[1].y), pack_h2(br[1].z, br[1].w));     \
        *(uint4*)((buf) + B_OFF + (sts) + 16) =                                   \
            make_uint4(pack_h2(br[2].x, br[2].y), pack_h2(br[2].z, br[2].w),      \
                       pack_h2(br[3].x, br[3].y), pack_h2(br[3].z, br[3].w));     \
    }

// GEMM1: h = silu(xn[gather] @ w1[e]^T)
__global__ void __launch_bounds__(256, 2) k_gemm1(const float* __restrict__ w1) {
    int e = blockIdx.z;
    int cnt = min(g_count[e], CAP);
    int m0 = blockIdx.y * 128;
    if (m0 >= cnt) return;
    int n0 = blockIdx.x * 128;

    extern __shared__ char sm[];
    __shared__ int stok[128];
    int t = threadIdx.x, lane = t & 31, w = t >> 5;
    if (t < 128) {
        int s = m0 + t;
        stok[t] = (s < cnt) ? g_row_tok[e * CAP + s] : -1;
    }
    __syncthreads();

    int row = t >> 1;
    int half = t & 1;
    int atok = stok[row];
    uint32_t asz = (atok >= 0) ? 16u : 0u;
    const __half* a_src = g_xnh + ((atok >= 0) ? (size_t)atok * H_DIM : 0) + half * 16;
    const float* b_src = w1 + ((size_t)e * D_FF + n0 + row) * H_DIM + half * 16;
    uint32_t smb = smem_u32(sm);
    uint32_t sts = row * RB + half * 32;

    int wm = (w & 1) * 64;
    int wn = (w >> 1) * 32;
    uint32_t lm = (lane & 15) * RB + ((lane >> 4) << 4);
    uint32_t aoff = A_OFF + wm * RB + lm;
    uint32_t boff = B_OFF + wn * RB + lm;

    const int NC = H_DIM / 32;  // 32

    float4 br[4];
    LDGB(br, b_src, 0);
    STSB(sm, sts, br);
    LDGB(br, b_src, 1);
#pragma unroll
    for (int s = 0; s < 2; s++) {
        uint32_t d = smb + s * STAGE + sts;
        cp16(d + A_OFF, a_src + s * 32, asz);
        cp16(d + A_OFF + 16, a_src + s * 32 + 8, asz);
        CP_COMMIT();
    }

    float acc[4][4][4];
#pragma unroll
    for (int mf = 0; mf < 4; mf++)
#pragma unroll
        for (int nf = 0; nf < 4; nf++)
#pragma unroll
            for (int k = 0; k < 4; k++) acc[mf][nf][k] = 0.0f;

    uint32_t rd = smb;                        // compute stage (c)
    char*    w1s = sm + STAGE;                // STSB stage (c+1)
    uint32_t w2s = smb + 2 * STAGE;           // cp.async stage (c+2)
    const uint32_t smt = smb + 3 * STAGE;
    char* const smt_p = sm + 3 * STAGE;

#pragma unroll 1
    for (int c = 0; c < NC; c++) {
        CP_WAIT1();
        __syncthreads();
        if (c + 1 < NC) STSB(w1s, sts, br);
        if (c + 2 < NC) {
            LDGB(br, b_src, c + 2);
            uint32_t d = w2s + sts;
            cp16(d + A_OFF, a_src + (c + 2) * 32, asz);
            cp16(d + A_OFF + 16, a_src + (c + 2) * 32 + 8, asz);
        }
        CP_COMMIT();
#pragma unroll
        for (int kk = 0; kk < 2; kk++) {
            uint32_t ko = kk * 32;
            uint32_t ah[4][4], bh[2][4];
#pragma unroll
            for (int mf = 0; mf < 4; mf++) ldsm4(ah[mf], rd + aoff + mf * (16 * RB) + ko);
#pragma unroll
            for (int g = 0; g < 2; g++) ldsm4(bh[g], rd + boff + g * (16 * RB) + ko);
#pragma unroll
            for (int mf = 0; mf < 4; mf++)
#pragma unroll
                for (int nf = 0; nf < 4; nf++)
                    mma_f16(acc[mf][nf], ah[mf], bh[nf >> 1][nf & 1], bh[nf >> 1][(nf & 1) + 2]);
        }
        rd += STAGE;  if (rd == smt) rd = smb;
        w1s += STAGE; if (w1s == smt_p) w1s = sm;
        w2s += STAGE; if (w2s == smt) w2s = smb;
    }

    int rbase = m0 + wm + (lane >> 2);
    size_t eb = (size_t)e * CAP;
#pragma unroll
    for (int mf = 0; mf < 4; mf++) {
#pragma unroll
        for (int nf = 0; nf < 4; nf++) {
            int col = n0 + wn + nf * 8 + (lane & 3) * 2;
#pragma unroll
            for (int hh = 0; hh < 2; hh++) {
                size_t r = eb + rbase + mf * 16 + hh * 8;
                float s0 = silu_f(acc[mf][nf][hh * 2]);
                float s1 = silu_f(acc[mf][nf][hh * 2 + 1]);
                *(uint32_t*)(g_hh + r * D_FF + col) = pack_h2(s0, s1);
            }
        }
    }
}

// GEMM2: od = h @ w2[e]^T  (od stored fp16)
__global__ void __launch_bounds__(256, 2) k_gemm2(const float* __restrict__ w2) {
    int e = blockIdx.z;
    int cnt = min(g_count[e], CAP);
    int m0 = blockIdx.y * 128;
    if (m0 >= cnt) return;
    int n0 = blockIdx.x * 128;

    extern __shared__ char sm[];
    int t = threadIdx.x, lane = t & 31, w = t >> 5;

    int row = t >> 1;
    int half = t & 1;
    const __half* a_src = g_hh + ((size_t)e * CAP + m0 + row) * D_FF + half * 16;
    const float* b_src = w2 + ((size_t)e * H_DIM + n0 + row) * D_FF + half * 16;
    uint32_t smb = smem_u32(sm);
    uint32_t sts = row * RB + half * 32;

    int wm = (w & 1) * 64;
    int wn = (w >> 1) * 32;
    uint32_t lm = (lane & 15) * RB + ((lane >> 4) << 4);
    uint32_t aoff = A_OFF + wm * RB + lm;
    uint32_t boff = B_OFF + wn * RB + lm;

    const int NC = D_FF / 32;  // 64

    float4 br[4];
    LDGB(br, b_src, 0);
    STSB(sm, sts, br);
    LDGB(br, b_src, 1);
#pragma unroll
    for (int s = 0; s < 2; s++) {
        uint32_t d = smb + s * STAGE + sts;
        cp16(d + A_OFF, a_src + s * 32, 16);
        cp16(d + A_OFF + 16, a_src + s * 32 + 8, 16);
        CP_COMMIT();
    }

    float acc[4][4][4];
#pragma unroll
    for (int mf = 0; mf < 4; mf++)
#pragma unroll
        for (int nf = 0; nf < 4; nf++)
#pragma unroll
            for (int k = 0; k < 4; k++) acc[mf][nf][k] = 0.0f;

    uint32_t rd = smb;
    char*    w1s = sm + STAGE;
    uint32_t w2s = smb + 2 * STAGE;
    const uint32_t smt = smb + 3 * STAGE;
    char* const smt_p = sm + 3 * STAGE;

#pragma unroll 1
    for (int c = 0; c < NC; c++) {
        CP_WAIT1();
        __syncthreads();
        if (c + 1 < NC) STSB(w1s, sts, br);
        if (c + 2 < NC) {
            LDGB(br, b_src, c + 2);
            uint32_t d = w2s + sts;
            cp16(d + A_OFF, a_src + (c + 2) * 32, 16);
            cp16(d + A_OFF + 16, a_src + (c + 2) * 32 + 8, 16);
        }
        CP_COMMIT();
#pragma unroll
        for (int kk = 0; kk < 2; kk++) {
            uint32_t ko = kk * 32;
            uint32_t ah[4][4], bh[2][4];
#pragma unroll
            for (int mf = 0; mf < 4; mf++) ldsm4(ah[mf], rd + aoff + mf * (16 * RB) + ko);
#pragma unroll
            for (int g = 0; g < 2; g++) ldsm4(bh[g], rd + boff + g * (16 * RB) + ko);
#pragma unroll
            for (int mf = 0; mf < 4; mf++)
#pragma unroll
                for (int nf = 0; nf < 4; nf++)
                    mma_f16(acc[mf][nf], ah[mf], bh[nf >> 1][nf & 1], bh[nf >> 1][(nf & 1) + 2]);
        }
        rd += STAGE;  if (rd == smt) rd = smb;
        w1s += STAGE; if (w1s == smt_p) w1s = sm;
        w2s += STAGE; if (w2s == smt) w2s = smb;
    }

    int rbase = m0 + wm + (lane >> 2);
    size_t eb = (size_t)e * CAP;
#pragma unroll
    for (int mf = 0; mf < 4; mf++) {
#pragma unroll
        for (int nf = 0; nf < 4; nf++) {
            int col = n0 + wn + nf * 8 + (lane & 3) * 2;
#pragma unroll
            for (int hh = 0; hh < 2; hh++) {
                size_t r = eb + rbase + mf * 16 + hh * 8;
                *(uint32_t*)(g_od + r * H_DIM + col) =
                    pack_h2(acc[mf][nf][hh * 2], acc[mf][nf][hh * 2 + 1]);
            }
        }
    }
}

// ---------------- 5: combine (od is fp16) --------------------------------------
__global__ void k_combine(const float* __restrict__ x, float* __restrict__ out) {
    int tok = blockIdx.x;
    int t = threadIdx.x;
    int p0 = g_pair_idx[tok * 2];
    int p1 = g_pair_idx[tok * 2 + 1];
    float w0 = g_pair_w[tok * 2];
    float w1 = g_pair_w[tok * 2 + 1];
    float4 v = ((const float4*)(x + (size_t)tok * H_DIM))[t];
    if (p0 >= 0) {
        uint2 u = *(const uint2*)(g_od + (size_t)p0 * H_DIM + t * 4);
        float2 a = __half22float2(*(__half2*)&u.x);
        float2 b = __half22float2(*(__half2*)&u.y);
        v.x += w0 * a.x; v.y += w0 * a.y; v.z += w0 * b.x; v.w += w0 * b.y;
    }
    if (p1 >= 0) {
        uint2 u = *(const uint2*)(g_od + (size_t)p1 * H_DIM + t * 4);
        float2 a = __half22float2(*(__half2*)&u.x);
        float2 b = __half22float2(*(__half2*)&u.y);
        v.x += w1 * a.x; v.y += w1 * a.y; v.z += w1 * b.x; v.w += w1 * b.y;
    }
    ((float4*)(out + (size_t)tok * H_DIM))[t] = v;
}

// ---------------- launch --------------------------------------------------------
extern "C" void kernel_launch(void* const* d_in, const int* in_sizes, int n_in,
                              void* d_out, int out_size) {
    const float* x        = (const float*)d_in[0];
    const float* rms_w    = (const float*)d_in[1];
    const float* router_w = (const float*)d_in[2];
    const float* w1       = (const float*)d_in[3];
    const float* w2       = (const float*)d_in[4];
    float* out = (float*)d_out;

    static bool attr_done = false;
    if (!attr_done) {
        cudaFuncSetAttribute(k_gemm1, cudaFuncAttributeMaxDynamicSharedMemorySize, SMEM_SZ);
        cudaFuncSetAttribute(k_gemm2, cudaFuncAttributeMaxDynamicSharedMemorySize, SMEM_SZ);
        attr_done = true;
    }

    k_rmsnorm<<<S_TOK, 256>>>(x, rms_w);
    k_router<<<S_TOK / 32, 256>>>(x, rms_w, router_w);
    k_gemm1<<<dim3(D_FF / 128, CAP / 128, N_EXP), 256, SMEM_SZ>>>(w1);
    k_gemm2<<<dim3(H_DIM / 128, CAP / 128, N_EXP), 256, SMEM_SZ>>>(w2);
    k_combine<<<S_TOK, 256>>>(x, out);
}

// round 17
// speedup vs baseline: 1.3096x; 1.0073x over previous
#include <cuda_runtime.h>
#include <cuda_fp16.h>
#include <math.h>
#include <stdint.h>

#define S_TOK 8192
#define H_DIM 1024
#define N_EXP 64
#define CAP 512
#define D_FF 2048
#define NROWS (N_EXP * CAP)  // 32768

// ---------------- scratch (device globals) ----------------------------------
__device__ float  g_scale[S_TOK];                 // rms scale per token
__device__ __half g_xnh[(size_t)S_TOK * H_DIM];   // 16 MB
__device__ __half g_hh[(size_t)NROWS * D_FF];     // 128 MB
__device__ __half g_od[(size_t)NROWS * H_DIM];    // 64 MB
__device__ int    g_row_tok[NROWS];
__device__ int    g_count[N_EXP];
__device__ int    g_pair_idx[S_TOK * 2];
__device__ float  g_pair_w[S_TOK * 2];

// ---------------- helpers -----------------------------------------------------
__device__ __forceinline__ uint32_t smem_u32(const void* p) {
    uint32_t a;
    asm("{ .reg .u64 t; cvta.to.shared.u64 t, %1; cvt.u32.u64 %0, t; }"
        : "=r"(a) : "l"(p));
    return a;
}
__device__ __forceinline__ void ldsm4(uint32_t* r, uint32_t addr) {
    asm volatile("ldmatrix.sync.aligned.m8n8.x4.shared.b16 {%0,%1,%2,%3}, [%4];"
                 : "=r"(r[0]), "=r"(r[1]), "=r"(r[2]), "=r"(r[3]) : "r"(addr));
}
__device__ __forceinline__ void mma_f16(float* d, const uint32_t* a,
                                        uint32_t b0, uint32_t b1) {
    asm volatile("mma.sync.aligned.m16n8k16.row.col.f32.f16.f16.f32 "
                 "{%0,%1,%2,%3}, {%4,%5,%6,%7}, {%8,%9}, {%0,%1,%2,%3};"
                 : "+f"(d[0]), "+f"(d[1]), "+f"(d[2]), "+f"(d[3])
                 : "r"(a[0]), "r"(a[1]), "r"(a[2]), "r"(a[3]), "r"(b0), "r"(b1));
}
__device__ __forceinline__ void cp16(uint32_t dst, const void* src, uint32_t sz) {
    asm volatile("cp.async.cg.shared.global [%0], [%1], 16, %2;"
                 :: "r"(dst), "l"(src), "r"(sz) : "memory");
}
#define CP_COMMIT() asm volatile("cp.async.commit_group;" ::: "memory")
#define CP_WAIT2()  asm volatile("cp.async.wait_group 2;" ::: "memory")

__device__ __forceinline__ uint32_t pack_h2(float a, float b) {
    __half2 t = __floats2half2_rn(a, b);
    return *reinterpret_cast<uint32_t*>(&t);
}
__device__ __forceinline__ float silu_f(float v) { return v / (1.0f + expf(-v)); }

// smem geometry: BK=32 fp16 per row = 64B payload, 80B stride (conflict-free)
#define RB 80
#define A_OFF 0
#define B_OFF (128 * RB)      // 10240
#define STAGE (2 * 128 * RB)  // 20480
#define NSTG 4
#define SMEM_SZ (NSTG * STAGE)  // 81920 (4-stage pipeline)

// ---------------- 1: RMSNorm (fp16 out + scale; block 0 zeroes counters) ------
__global__ void k_rmsnorm(const float* __restrict__ x, const float* __restrict__ w) {
    int tok = blockIdx.x;
    int t = threadIdx.x;
    if (blockIdx.x == 0 && t < N_EXP) g_count[t] = 0;
    float4 v = ((const float4*)(x + (size_t)tok * H_DIM))[t];
    float ss = v.x * v.x + v.y * v.y + v.z * v.z + v.w * v.w;
#pragma unroll
    for (int o = 16; o > 0; o >>= 1) ss += __shfl_xor_sync(0xffffffffu, ss, o);
    __shared__ float red[8];
    if ((t & 31) == 0) red[t >> 5] = ss;
    __syncthreads();
    float tot = red[0] + red[1] + red[2] + red[3] + red[4] + red[5] + red[6] + red[7];
    float scale = rsqrtf(tot * (1.0f / H_DIM) + 1e-6f);
    if (t == 0) g_scale[tok] = scale;
    float4 wv = ((const float4*)w)[t];
    float4 o;
    o.x = v.x * scale * wv.x; o.y = v.y * scale * wv.y;
    o.z = v.z * scale * wv.z; o.w = v.w * scale * wv.w;
    uint2 H;
    H.x = pack_h2(o.x, o.y); H.y = pack_h2(o.z, o.w);
    *(uint2*)(g_xnh + (size_t)tok * H_DIM + t * 4) = H;
}

// ---------------- 2: router + top2 + slot assign ------------------------------
// 256 blocks x 32 tokens, fp32 (routing must match fp32 reference).
// Reads x directly; As = (x*scale)*rms_w — bit-identical to rmsnorm's xn.
__global__ void k_router(const float* __restrict__ x,
                         const float* __restrict__ rms_w,
                         const float* __restrict__ rw) {
    __shared__ float As[2][32][33];
    __shared__ float Bs[2][32][65];
    __shared__ float Ss[32][65];
    int t = threadIdx.x;
    int tok0 = blockIdx.x * 32;
    int ty = t >> 4, tx = t & 15;
    float acc[2][4];
#pragma unroll
    for (int i = 0; i < 2; i++)
#pragma unroll
        for (int j = 0; j < 4; j++) acc[i][j] = 0.0f;

    int lrA = t >> 3;
    int lkA = (t & 7) * 4;
    int lrB = t >> 2;
    int lkB = (t & 3) * 8;
    const float* ap = x + (size_t)(tok0 + lrA) * H_DIM + lkA;
    const float* wp = rms_w + lkA;
    const float* bp = rw + (size_t)lrB * H_DIM + lkB;
    float scaleA = g_scale[tok0 + lrA];

    float4 pa = *(const float4*)(ap);
    float4 pw = *(const float4*)(wp);
    float4 pb0 = *(const float4*)(bp);
    float4 pb1 = *(const float4*)(bp + 4);
    As[0][lkA + 0][lrA] = pa.x * scaleA * pw.x;
    As[0][lkA + 1][lrA] = pa.y * scaleA * pw.y;
    As[0][lkA + 2][lrA] = pa.z * scaleA * pw.z;
    As[0][lkA + 3][lrA] = pa.w * scaleA * pw.w;
    Bs[0][lkB + 0][lrB] = pb0.x; Bs[0][lkB + 1][lrB] = pb0.y;
    Bs[0][lkB + 2][lrB] = pb0.z; Bs[0][lkB + 3][lrB] = pb0.w;
    Bs[0][lkB + 4][lrB] = pb1.x; Bs[0][lkB + 5][lrB] = pb1.y;
    Bs[0][lkB + 6][lrB] = pb1.z; Bs[0][lkB + 7][lrB] = pb1.w;
    __syncthreads();

    const int NCH = H_DIM / 32;  // 32
#pragma unroll 1
    for (int c = 0; c < NCH; c++) {
        int cur = c & 1;
        if (c + 1 < NCH) {
            pa = *(const float4*)(ap + (c + 1) * 32);
            pw = *(const float4*)(wp + (c + 1) * 32);
            pb0 = *(const float4*)(bp + (c + 1) * 32);
            pb1 = *(const float4*)(bp + (c + 1) * 32 + 4);
        }
#pragma unroll
        for (int kk = 0; kk < 32; kk++) {
            float a[2], b[4];
#pragma unroll
            for (int i = 0; i < 2; i++) a[i] = As[cur][kk][ty * 2 + i];
#pragma unroll
            for (int j = 0; j < 4; j++) b[j] = Bs[cur][kk][tx * 4 + j];
#pragma unroll
            for (int i = 0; i < 2; i++)
#pragma unroll
                for (int j = 0; j < 4; j++) acc[i][j] = fmaf(a[i], b[j], acc[i][j]);
        }
        if (c + 1 < NCH) {
            int nxt = cur ^ 1;
            As[nxt][lkA + 0][lrA] = pa.x * scaleA * pw.x;
            As[nxt][lkA + 1][lrA] = pa.y * scaleA * pw.y;
            As[nxt][lkA + 2][lrA] = pa.z * scaleA * pw.z;
            As[nxt][lkA + 3][lrA] = pa.w * scaleA * pw.w;
            Bs[nxt][lkB + 0][lrB] = pb0.x; Bs[nxt][lkB + 1][lrB] = pb0.y;
            Bs[nxt][lkB + 2][lrB] = pb0.z; Bs[nxt][lkB + 3][lrB] = pb0.w;
            Bs[nxt][lkB + 4][lrB] = pb1.x; Bs[nxt][lkB + 5][lrB] = pb1.y;
            Bs[nxt][lkB + 6][lrB] = pb1.z; Bs[nxt][lkB + 7][lrB] = pb1.w;
        }
        __syncthreads();
    }

#pragma unroll
    for (int i = 0; i < 2; i++)
#pragma unroll
        for (int j = 0; j < 4; j++) Ss[ty * 2 + i][tx * 4 + j] = acc[i][j];
    __syncthreads();

    if (t < 32) {
        int tok = tok0 + t;
        float v1 = -1e30f, v2 = -1e30f;
        int i1 = 0, i2 = 0;
#pragma unroll 4
        for (int e = 0; e < N_EXP; e++) {
            float s = Ss[t][e];
            if (s > v1) { v2 = v1; i2 = i1; v1 = s; i1 = e; }
            else if (s > v2) { v2 = s; i2 = e; }
        }
        float ex = expf(v2 - v1);
        float wB = ex / (1.0f + ex);
        float wA = 1.0f - wB;

        int s1 = atomicAdd(&g_count[i1], 1);
        if (s1 < CAP) {
            g_row_tok[i1 * CAP + s1] = tok;
            g_pair_idx[tok * 2] = i1 * CAP + s1;
            g_pair_w[tok * 2] = wA;
        } else g_pair_idx[tok * 2] = -1;
        int s2 = atomicAdd(&g_count[i2], 1);
        if (s2 < CAP) {
            g_row_tok[i2 * CAP + s2] = tok;
            g_pair_idx[tok * 2 + 1] = i2 * CAP + s2;
            g_pair_w[tok * 2 + 1] = wB;
        } else g_pair_idx[tok * 2 + 1] = -1;
    }
}

// ---------------- GEMM core: fp16, A via cp.async (4-stage), B fused cvt ------
// CTA 128x128, 256 threads, 8 warps (2 wm x 4 wn), warp tile 64x32, BK=32.
// A: 4-stage cp.async ring, wait_group 2 (2 chunks in flight).
// B: LDG.128 prefetch 1 ahead -> cvt -> STS into stage c+1.

#define LDGB(dst, src, c)                                     \
    {                                                         \
        const float4* _p = (const float4*)((src) + (c) * 32); \
        dst[0] = _p[0]; dst[1] = _p[1];                        \
        dst[2] = _p[2]; dst[3] = _p[3];                        \
    }
#define STSB(buf, sts, br)                                                        \
    {                                                                             \
        *(uint4*)((buf) + B_OFF + (sts)) =                                        \
            make_uint4(pack_h2(br[0].x, br[0].y), pack_h2(br[0].z, br[0].w),      \
                       pack_h2(br[1].x, br[1].y), pack_h2(br[1].z, br[1].w));     \
        *(uint4*)((buf) + B_OFF + (sts) + 16) =                                   \
            make_uint4(pack_h2(br[2].x, br[2].y), pack_h2(br[2].z, br[2].w),      \
                       pack_h2(br[3].x, br[3].y), pack_h2(br[3].z, br[3].w));     \
    }

// GEMM1: h = silu(xn[gather] @ w1[e]^T)
__global__ void __launch_bounds__(256, 2) k_gemm1(const float* __restrict__ w1) {
    int e = blockIdx.z;
    int cnt = min(g_count[e], CAP);
    int m0 = blockIdx.y * 128;
    if (m0 >= cnt) return;
    int n0 = blockIdx.x * 128;

    extern __shared__ char sm[];
    __shared__ int stok[128];
    int t = threadIdx.x, lane = t & 31, w = t >> 5;
    if (t < 128) {
        int s = m0 + t;
        stok[t] = (s < cnt) ? g_row_tok[e * CAP + s] : -1;
    }
    __syncthreads();

    int row = t >> 1;
    int half = t & 1;
    int atok = stok[row];
    uint32_t asz = (atok >= 0) ? 16u : 0u;
    const __half* a_src = g_xnh + ((atok >= 0) ? (size_t)atok * H_DIM : 0) + half * 16;
    const float* b_src = w1 + ((size_t)e * D_FF + n0 + row) * H_DIM + half * 16;
    uint32_t smb = smem_u32(sm);
    uint32_t sts = row * RB + half * 32;

    int wm = (w & 1) * 64;
    int wn = (w >> 1) * 32;
    uint32_t lm = (lane & 15) * RB + ((lane >> 4) << 4);
    uint32_t aoff = A_OFF + wm * RB + lm;
    uint32_t boff = B_OFF + wn * RB + lm;

    const int NC = H_DIM / 32;  // 32

    float4 br[4];
    LDGB(br, b_src, 0);
    STSB(sm, sts, br);
    LDGB(br, b_src, 1);
#pragma unroll
    for (int s = 0; s < 3; s++) {
        uint32_t d = smb + s * STAGE + sts;
        cp16(d + A_OFF, a_src + s * 32, asz);
        cp16(d + A_OFF + 16, a_src + s * 32 + 8, asz);
        CP_COMMIT();
    }

    float acc[4][4][4];
#pragma unroll
    for (int mf = 0; mf < 4; mf++)
#pragma unroll
        for (int nf = 0; nf < 4; nf++)
#pragma unroll
            for (int k = 0; k < 4; k++) acc[mf][nf][k] = 0.0f;

    uint32_t rd = smb;                        // compute stage (c)
    char*    w1s = sm + STAGE;                // STSB stage (c+1)
    uint32_t w3s = smb + 3 * STAGE;           // cp.async stage (c+3)
    const uint32_t smt = smb + NSTG * STAGE;
    char* const smt_p = sm + NSTG * STAGE;

#pragma unroll 1
    for (int c = 0; c < NC; c++) {
        CP_WAIT2();
        __syncthreads();
        if (c + 1 < NC) STSB(w1s, sts, br);
        if (c + 2 < NC) LDGB(br, b_src, c + 2);
        if (c + 3 < NC) {
            uint32_t d = w3s + sts;
            cp16(d + A_OFF, a_src + (c + 3) * 32, asz);
            cp16(d + A_OFF + 16, a_src + (c + 3) * 32 + 8, asz);
        }
        CP_COMMIT();
#pragma unroll
        for (int kk = 0; kk < 2; kk++) {
            uint32_t ko = kk * 32;
            uint32_t ah[4][4], bh[2][4];
#pragma unroll
            for (int mf = 0; mf < 4; mf++) ldsm4(ah[mf], rd + aoff + mf * (16 * RB) + ko);
#pragma unroll
            for (int g = 0; g < 2; g++) ldsm4(bh[g], rd + boff + g * (16 * RB) + ko);
#pragma unroll
            for (int mf = 0; mf < 4; mf++)
#pragma unroll
                for (int nf = 0; nf < 4; nf++)
                    mma_f16(acc[mf][nf], ah[mf], bh[nf >> 1][nf & 1], bh[nf >> 1][(nf & 1) + 2]);
        }
        rd += STAGE;  if (rd == smt) rd = smb;
        w1s += STAGE; if (w1s == smt_p) w1s = sm;
        w3s += STAGE; if (w3s == smt) w3s = smb;
    }

    int rbase = m0 + wm + (lane >> 2);
    size_t eb = (size_t)e * CAP;
#pragma unroll
    for (int mf = 0; mf < 4; mf++) {
#pragma unroll
        for (int nf = 0; nf < 4; nf++) {
            int col = n0 + wn + nf * 8 + (lane & 3) * 2;
#pragma unroll
            for (int hh = 0; hh < 2; hh++) {
                size_t r = eb + rbase + mf * 16 + hh * 8;
                float s0 = silu_f(acc[mf][nf][hh * 2]);
                float s1 = silu_f(acc[mf][nf][hh * 2 + 1]);
                *(uint32_t*)(g_hh + r * D_FF + col) = pack_h2(s0, s1);
            }
        }
    }
}

// GEMM2: od = h @ w2[e]^T  (od stored fp16)
__global__ void __launch_bounds__(256, 2) k_gemm2(const float* __restrict__ w2) {
    int e = blockIdx.z;
    int cnt = min(g_count[e], CAP);
    int m0 = blockIdx.y * 128;
    if (m0 >= cnt) return;
    int n0 = blockIdx.x * 128;

    extern __shared__ char sm[];
    int t = threadIdx.x, lane = t & 31, w = t >> 5;

    int row = t >> 1;
    int half = t & 1;
    const __half* a_src = g_hh + ((size_t)e * CAP + m0 + row) * D_FF + half * 16;
    const float* b_src = w2 + ((size_t)e * H_DIM + n0 + row) * D_FF + half * 16;
    uint32_t smb = smem_u32(sm);
    uint32_t sts = row * RB + half * 32;

    int wm = (w & 1) * 64;
    int wn = (w >> 1) * 32;
    uint32_t lm = (lane & 15) * RB + ((lane >> 4) << 4);
    uint32_t aoff = A_OFF + wm * RB + lm;
    uint32_t boff = B_OFF + wn * RB + lm;

    const int NC = D_FF / 32;  // 64

    float4 br[4];
    LDGB(br, b_src, 0);
    STSB(sm, sts, br);
    LDGB(br, b_src, 1);
#pragma unroll
    for (int s = 0; s < 3; s++) {
        uint32_t d = smb + s * STAGE + sts;
        cp16(d + A_OFF, a_src + s * 32, 16);
        cp16(d + A_OFF + 16, a_src + s * 32 + 8, 16);
        CP_COMMIT();
    }

    float acc[4][4][4];
#pragma unroll
    for (int mf = 0; mf < 4; mf++)
#pragma unroll
        for (int nf = 0; nf < 4; nf++)
#pragma unroll
            for (int k = 0; k < 4; k++) acc[mf][nf][k] = 0.0f;

    uint32_t rd = smb;
    char*    w1s = sm + STAGE;
    uint32_t w3s = smb + 3 * STAGE;
    const uint32_t smt = smb + NSTG * STAGE;
    char* const smt_p = sm + NSTG * STAGE;

#pragma unroll 1
    for (int c = 0; c < NC; c++) {
        CP_WAIT2();
        __syncthreads();
        if (c + 1 < NC) STSB(w1s, sts, br);
        if (c + 2 < NC) LDGB(br, b_src, c + 2);
        if (c + 3 < NC) {
            uint32_t d = w3s + sts;
            cp16(d + A_OFF, a_src + (c + 3) * 32, 16);
            cp16(d + A_OFF + 16, a_src + (c + 3) * 32 + 8, 16);
        }
        CP_COMMIT();
#pragma unroll
        for (int kk = 0; kk < 2; kk++) {
            uint32_t ko = kk * 32;
            uint32_t ah[4][4], bh[2][4];
#pragma unroll
            for (int mf = 0; mf < 4; mf++) ldsm4(ah[mf], rd + aoff + mf * (16 * RB) + ko);
#pragma unroll
            for (int g = 0; g < 2; g++) ldsm4(bh[g], rd + boff + g * (16 * RB) + ko);
#pragma unroll
            for (int mf = 0; mf < 4; mf++)
#pragma unroll
                for (int nf = 0; nf < 4; nf++)
                    mma_f16(acc[mf][nf], ah[mf], bh[nf >> 1][nf & 1], bh[nf >> 1][(nf & 1) + 2]);
        }
        rd += STAGE;  if (rd == smt) rd = smb;
        w1s += STAGE; if (w1s == smt_p) w1s = sm;
        w3s += STAGE; if (w3s == smt) w3s = smb;
    }

    int rbase = m0 + wm + (lane >> 2);
    size_t eb = (size_t)e * CAP;
#pragma unroll
    for (int mf = 0; mf < 4; mf++) {
#pragma unroll
        for (int nf = 0; nf < 4; nf++) {
            int col = n0 + wn + nf * 8 + (lane & 3) * 2;
#pragma unroll
            for (int hh = 0; hh < 2; hh++) {
                size_t r = eb + rbase + mf * 16 + hh * 8;
                *(uint32_t*)(g_od + r * H_DIM + col) =
                    pack_h2(acc[mf][nf][hh * 2], acc[mf][nf][hh * 2 + 1]);
            }
        }
    }
}

// ---------------- 5: combine (od is fp16) --------------------------------------
__global__ void k_combine(const float* __restrict__ x, float* __restrict__ out) {
    int tok = blockIdx.x;
    int t = threadIdx.x;
    int p0 = g_pair_idx[tok * 2];
    int p1 = g_pair_idx[tok * 2 + 1];
    float w0 = g_pair_w[tok * 2];
    float w1 = g_pair_w[tok * 2 + 1];
    float4 v = ((const float4*)(x + (size_t)tok * H_DIM))[t];
    if (p0 >= 0) {
        uint2 u = *(const uint2*)(g_od + (size_t)p0 * H_DIM + t * 4);
        float2 a = __half22float2(*(__half2*)&u.x);
        float2 b = __half22float2(*(__half2*)&u.y);
        v.x += w0 * a.x; v.y += w0 * a.y; v.z += w0 * b.x; v.w += w0 * b.y;
    }
    if (p1 >= 0) {
        uint2 u = *(const uint2*)(g_od + (size_t)p1 * H_DIM + t * 4);
        float2 a = __half22float2(*(__half2*)&u.x);
        float2 b = __half22float2(*(__half2*)&u.y);
        v.x += w1 * a.x; v.y += w1 * a.y; v.z += w1 * b.x; v.w += w1 * b.y;
    }
    ((float4*)(out + (size_t)tok * H_DIM))[t] = v;
}

// ---------------- launch --------------------------------------------------------
extern "C" void kernel_launch(void* const* d_in, const int* in_sizes, int n_in,
                              void* d_out, int out_size) {
    const float* x        = (const float*)d_in[0];
    const float* rms_w    = (const float*)d_in[1];
    const float* router_w = (const float*)d_in[2];
    const float* w1       = (const float*)d_in[3];
    const float* w2       = (const float*)d_in[4];
    float* out = (float*)d_out;

    static bool attr_done = false;
    if (!attr_done) {
        cudaFuncSetAttribute(k_gemm1, cudaFuncAttributeMaxDynamicSharedMemorySize, SMEM_SZ);
        cudaFuncSetAttribute(k_gemm2, cudaFuncAttributeMaxDynamicSharedMemorySize, SMEM_SZ);
        attr_done = true;
    }

    k_rmsnorm<<<S_TOK, 256>>>(x, rms_w);
    k_router<<<S_TOK / 32, 256>>>(x, rms_w, router_w);
    k_gemm1<<<dim3(D_FF / 128, CAP / 128, N_EXP), 256, SMEM_SZ>>>(w1);
    k_gemm2<<<dim3(H_DIM / 128, CAP / 128, N_EXP), 256, SMEM_SZ>>>(w2);
    k_combine<<<S_TOK, 256>>>(x, out);
}